// round 7
// baseline (speedup 1.0000x reference)
#include <cuda_runtime.h>

#define BATCH 128
#define SEQ   256
#define UNITS 128
#define NV    512          // 4*UNITS gate width
#define DEPTH 655
#define KROWS 2620         // 4*DEPTH
#define NT    256          // threads per lstm block
#define ROWS_PB 2          // batch rows per block
#define GRID  (BATCH / ROWS_PB)
#define RROWS 80           // Wh rows register-resident per column
#define SROWS (UNITS - RROWS)   // 48 rows in smem
#define RPAIR (RROWS / 2)       // 40 row-pairs per column in registers
#define RGRP4 (RROWS / 4)       // 20 register groups of 4 rows
#define SGRP4 (SROWS / 4)       // 12 smem groups of 4 rows

// Precomputed M = W_dense @ Wx  [KROWS][NV], plus row KROWS = b_dense@Wx + b_lstm
__device__ float g_M[(KROWS + 1) * NV];

typedef unsigned long long ull;

#define FMA2(acc, a, b) \
    asm("fma.rn.f32x2 %0, %1, %2, %0;" : "+l"(acc) : "l"(a), "l"(b))

__device__ __forceinline__ ull pk(float lo, float hi) {
    return (ull)__float_as_uint(lo) | ((ull)__float_as_uint(hi) << 32);
}
__device__ __forceinline__ float red2(ull a, ull b) {
    ull s;
    asm("add.rn.f32x2 %0, %1, %2;" : "=l"(s) : "l"(a), "l"(b));
    return __uint_as_float((unsigned)s) + __uint_as_float((unsigned)(s >> 32));
}
__device__ __forceinline__ float sigmoid_f(float x) {
    return __fdividef(1.f, 1.f + __expf(-x));
}
__device__ __forceinline__ float tanh_f(float x) {
    return 1.f - __fdividef(2.f, __expf(2.f * x) + 1.f);
}

// ---------------------------------------------------------------------------
__global__ void prep_bb_kernel(const float* __restrict__ b_dense,
                               const float* __restrict__ Wx,
                               const float* __restrict__ b_lstm) {
    int t = threadIdx.x;
    float acc = 0.f;
#pragma unroll 8
    for (int u = 0; u < UNITS; ++u)
        acc = fmaf(b_dense[u], Wx[u * NV + t], acc);
    g_M[KROWS * NV + t] = acc + b_lstm[t];
}

// ---------------------------------------------------------------------------
#define RPB 20
__global__ __launch_bounds__(512) void prep_M_kernel(const float* __restrict__ Wd,
                                                     const float* __restrict__ Wx) {
    __shared__ float wd[RPB * UNITS];
    const int t = threadIdx.x;
    const int r0 = blockIdx.x * RPB;
    for (int idx = t; idx < RPB * UNITS; idx += 512)
        wd[idx] = Wd[r0 * UNITS + idx];
    __syncthreads();

    float acc[RPB];
#pragma unroll
    for (int r = 0; r < RPB; ++r) acc[r] = 0.f;

    for (int u = 0; u < UNITS; u += 4) {
        float x0 = Wx[(u + 0) * NV + t];
        float x1 = Wx[(u + 1) * NV + t];
        float x2 = Wx[(u + 2) * NV + t];
        float x3 = Wx[(u + 3) * NV + t];
#pragma unroll
        for (int r = 0; r < RPB; ++r) {
            float4 w = *(const float4*)&wd[r * UNITS + u];
            acc[r] = fmaf(w.x, x0, fmaf(w.y, x1, fmaf(w.z, x2, fmaf(w.w, x3, acc[r]))));
        }
    }
#pragma unroll
    for (int r = 0; r < RPB; ++r)
        g_M[(r0 + r) * NV + t] = acc[r];
}

// ---------------------------------------------------------------------------
__global__ void ctx_kernel(const int* __restrict__ last_rule,
                           const int* __restrict__ move_count,
                           const int* __restrict__ node_count,
                           const int* __restrict__ problem_type,
                           float* __restrict__ out, int out_size) {
    const int b = blockIdx.x, j = threadIdx.x;
    if (j < 35) {
        float v;
        if (j == 0)      v = (float)last_rule[b];
        else if (j == 1) v = (float)move_count[b];
        else if (j == 2) v = (float)node_count[b];
        else             v = (problem_type[b] == (j - 3)) ? 1.f : 0.f;
        out[b * 35 + j] = v;
    }
    const int seq_off = BATCH * 35 + BATCH * UNITS + BATCH * SEQ * UNITS;
    if (b == 0 && j == 63 && out_size > seq_off)
        out[seq_off] = (float)SEQ;
}

// ---------------------------------------------------------------------------
// LSTM: one block per TWO batch rows; 256 threads. Warp w covers elements
// [16w,16w+16). Lane l<16 owns element e with gate cols (e, e+256)=(i,g);
// lane l+16 owns (e+128, e+384)=(f,o). Weight registers and smem weights are
// shared by both batch rows (2x arithmetic intensity per weight access).
// Two shfl.xor(16) per row deliver f,o to the (i,g) lane; c,h in registers.
// h published via per-row ping-pong smem -> ONE __syncthreads per step.
// ---------------------------------------------------------------------------
#define WH_HALF (SGRP4 * NT * 16)      // 48 KB per column-set
#define SMEM_LSTM (2 * WH_HALF + 4 * UNITS * 4 + ROWS_PB * 4 * SEQ * 4)

__global__ __launch_bounds__(NT, 1) void lstm_kernel(
    const int* __restrict__ bwd, const int* __restrict__ fwd,
    const int* __restrict__ lbwd, const int* __restrict__ lfwd,
    const float* __restrict__ Wh,
    float* __restrict__ out_h,    // [B][S][UNITS]
    float* __restrict__ out_lv) { // [B][UNITS]
    extern __shared__ unsigned char smraw[];
    ulonglong2* whA = (ulonglong2*)smraw;
    ulonglong2* whB = (ulonglong2*)(smraw + WH_HALF);
    float*      hbuf = (float*)(smraw + 2 * WH_HALF);  // [2 rows][2 pp][128]
    int*        idx_s = (int*)(hbuf + 4 * UNITS);      // [2 rows][4*SEQ]

    const int b0 = blockIdx.x * ROWS_PB;
    const int t = threadIdx.x;
    const int l = t & 31;
    const int role = l >> 4;                 // 0: (i,g) owner, 1: (f,o) owner
    const int e  = (t >> 5) * 16 + (l & 15); // element in [0,128)
    const int cA = e + role * 128;           // i (role0) / f (role1)
    const int cB = cA + 256;                 // g (role0) / o (role1)

    // ---- weights: rows [0,RROWS) -> register pairs per column ----
    ull wA[RPAIR], wB[RPAIR];
#pragma unroll
    for (int p = 0; p < RPAIR; ++p) {
        int i = 2 * p;
        wA[p] = pk(Wh[i * NV + cA], Wh[(i + 1) * NV + cA]);
        wB[p] = pk(Wh[i * NV + cB], Wh[(i + 1) * NV + cB]);
    }
#pragma unroll
    for (int g = 0; g < SGRP4; ++g) {
        int i = RROWS + 4 * g;
        ulonglong2 vA, vB;
        vA.x = pk(Wh[i * NV + cA],       Wh[(i + 1) * NV + cA]);
        vA.y = pk(Wh[(i + 2) * NV + cA], Wh[(i + 3) * NV + cA]);
        vB.x = pk(Wh[i * NV + cB],       Wh[(i + 1) * NV + cB]);
        vB.y = pk(Wh[(i + 2) * NV + cB], Wh[(i + 3) * NV + cB]);
        whA[g * NT + t] = vA;
        whB[g * NT + t] = vB;
    }

    // ---- stage gather indices for both rows ----
#pragma unroll
    for (int r = 0; r < ROWS_PB; ++r) {
        int* ix = idx_s + r * 4 * SEQ;
        ix[t]           = bwd[(b0 + r) * SEQ + t];
        ix[SEQ + t]     = DEPTH     + fwd[(b0 + r) * SEQ + t];
        ix[2 * SEQ + t] = 2 * DEPTH + lbwd[(b0 + r) * SEQ + t];
        ix[3 * SEQ + t] = 3 * DEPTH + lfwd[(b0 + r) * SEQ + t];
    }
    if (t < UNITS) { hbuf[t] = 0.f; hbuf[2 * UNITS + t] = 0.f; }
    float c0r = 0.f, c1r = 0.f, hl0 = 0.f, hl1 = 0.f;
    const float bbA = g_M[KROWS * NV + cA];
    const float bbB = g_M[KROWS * NV + cB];
    __syncthreads();

    const int* ix0 = idx_s;
    const int* ix1 = idx_s + 4 * SEQ;

    // xz for s = 0, both rows both columns
    float xzA0 = g_M[ix0[0] * NV + cA] + g_M[ix0[SEQ] * NV + cA] +
                 g_M[ix0[2 * SEQ] * NV + cA] + g_M[ix0[3 * SEQ] * NV + cA] + bbA;
    float xzB0 = g_M[ix0[0] * NV + cB] + g_M[ix0[SEQ] * NV + cB] +
                 g_M[ix0[2 * SEQ] * NV + cB] + g_M[ix0[3 * SEQ] * NV + cB] + bbB;
    float xzA1 = g_M[ix1[0] * NV + cA] + g_M[ix1[SEQ] * NV + cA] +
                 g_M[ix1[2 * SEQ] * NV + cA] + g_M[ix1[3 * SEQ] * NV + cA] + bbA;
    float xzB1 = g_M[ix1[0] * NV + cB] + g_M[ix1[SEQ] * NV + cB] +
                 g_M[ix1[2 * SEQ] * NV + cB] + g_M[ix1[3 * SEQ] * NV + cB] + bbB;

    for (int s = 0; s < SEQ; ++s) {
        // prefetch next step's xz components (L2-resident table)
        const int sn = (s + 1 < SEQ) ? s + 1 : s;
        float pA0 = g_M[ix0[sn] * NV + cA] + g_M[ix0[SEQ + sn] * NV + cA];
        float qA0 = g_M[ix0[2 * SEQ + sn] * NV + cA] + g_M[ix0[3 * SEQ + sn] * NV + cA];
        float pB0 = g_M[ix0[sn] * NV + cB] + g_M[ix0[SEQ + sn] * NV + cB];
        float qB0 = g_M[ix0[2 * SEQ + sn] * NV + cB] + g_M[ix0[3 * SEQ + sn] * NV + cB];
        float pA1 = g_M[ix1[sn] * NV + cA] + g_M[ix1[SEQ + sn] * NV + cA];
        float qA1 = g_M[ix1[2 * SEQ + sn] * NV + cA] + g_M[ix1[3 * SEQ + sn] * NV + cA];
        float pB1 = g_M[ix1[sn] * NV + cB] + g_M[ix1[SEQ + sn] * NV + cB];
        float qB1 = g_M[ix1[2 * SEQ + sn] * NV + cB] + g_M[ix1[3 * SEQ + sn] * NV + cB];

        // matvec for both rows: weight regs / smem shared across rows
        const int pp = s & 1;
        const ulonglong2* hp0 = (const ulonglong2*)(hbuf + pp * UNITS);
        const ulonglong2* hp1 = (const ulonglong2*)(hbuf + (2 + pp) * UNITS);
        ull aA00 = pk(xzA0, 0.f), aA01 = 0ull, aB00 = pk(xzB0, 0.f), aB01 = 0ull;
        ull aA10 = pk(xzA1, 0.f), aA11 = 0ull, aB10 = pk(xzB1, 0.f), aB11 = 0ull;
#pragma unroll
        for (int g = 0; g < RGRP4; ++g) {       // 20 groups x 4 rows = 80 rows
            ulonglong2 h0v = hp0[g];
            ulonglong2 h1v = hp1[g];
            ull w0 = wA[2 * g], w1 = wA[2 * g + 1];
            ull w2 = wB[2 * g], w3 = wB[2 * g + 1];
            FMA2(aA00, h0v.x, w0); FMA2(aA01, h0v.y, w1);
            FMA2(aB00, h0v.x, w2); FMA2(aB01, h0v.y, w3);
            FMA2(aA10, h1v.x, w0); FMA2(aA11, h1v.y, w1);
            FMA2(aB10, h1v.x, w2); FMA2(aB11, h1v.y, w3);
        }
#pragma unroll
        for (int g = 0; g < SGRP4; ++g) {       // 12 groups x 4 rows = 48 rows
            ulonglong2 h0v = hp0[RGRP4 + g];
            ulonglong2 h1v = hp1[RGRP4 + g];
            ulonglong2 vA = whA[g * NT + t];
            ulonglong2 vB = whB[g * NT + t];
            FMA2(aA00, h0v.x, vA.x); FMA2(aA01, h0v.y, vA.y);
            FMA2(aB00, h0v.x, vB.x); FMA2(aB01, h0v.y, vB.y);
            FMA2(aA10, h1v.x, vA.x); FMA2(aA11, h1v.y, vA.y);
            FMA2(aB10, h1v.x, vB.x); FMA2(aB11, h1v.y, vB.y);
        }
        float zA0 = red2(aA00, aA01), zB0 = red2(aB00, aB01);
        float zA1 = red2(aA10, aA11), zB1 = red2(aB10, aB11);

        float actA0 = sigmoid_f(zA0);
        float actB0 = role ? sigmoid_f(zB0) : tanh_f(zB0);
        float actA1 = sigmoid_f(zA1);
        float actB1 = role ? sigmoid_f(zB1) : tanh_f(zB1);

        float xf0 = __shfl_xor_sync(0xffffffffu, actA0, 16);
        float xo0 = __shfl_xor_sync(0xffffffffu, actB0, 16);
        float xf1 = __shfl_xor_sync(0xffffffffu, actA1, 16);
        float xo1 = __shfl_xor_sync(0xffffffffu, actB1, 16);

        float* hw0 = hbuf + (pp ^ 1) * UNITS;
        float* hw1 = hbuf + (2 + (pp ^ 1)) * UNITS;
        if (role == 0) {
            float cn0 = fmaf(xf0, c0r, actA0 * actB0);
            c0r = cn0;
            float hn0 = xo0 * tanh_f(cn0);
            hw0[e] = hn0;
            out_h[(b0 * SEQ + s) * UNITS + e] = hn0;
            hl0 = hn0;

            float cn1 = fmaf(xf1, c1r, actA1 * actB1);
            c1r = cn1;
            float hn1 = xo1 * tanh_f(cn1);
            hw1[e] = hn1;
            out_h[((b0 + 1) * SEQ + s) * UNITS + e] = hn1;
            hl1 = hn1;
        }
        xzA0 = pA0 + qA0 + bbA;
        xzB0 = pB0 + qB0 + bbB;
        xzA1 = pA1 + qA1 + bbA;
        xzB1 = pB1 + qB1 + bbB;
        __syncthreads();
    }
    if (role == 0) {
        out_lv[b0 * UNITS + e] = hl0;
        out_lv[(b0 + 1) * UNITS + e] = hl1;
    }
}

// ---------------------------------------------------------------------------
extern "C" void kernel_launch(void* const* d_in, const int* in_sizes, int n_in,
                              void* d_out, int out_size) {
    const int*   move_count   = (const int*)d_in[0];
    // d_in[1] = moves_remaining (unused by reference)
    const int*   last_rule    = (const int*)d_in[2];
    const int*   node_count   = (const int*)d_in[3];
    const int*   problem_type = (const int*)d_in[4];
    const int*   bwd          = (const int*)d_in[5];
    const int*   fwd          = (const int*)d_in[6];
    const int*   lbwd         = (const int*)d_in[7];
    const int*   lfwd         = (const int*)d_in[8];
    const float* Wd           = (const float*)d_in[9];
    const float* b_dense      = (const float*)d_in[10];
    const float* Wx           = (const float*)d_in[11];
    const float* Wh           = (const float*)d_in[12];
    const float* b_lstm       = (const float*)d_in[13];
    float* out = (float*)d_out;

    cudaFuncSetAttribute(lstm_kernel, cudaFuncAttributeMaxDynamicSharedMemorySize,
                         SMEM_LSTM);

    prep_bb_kernel<<<1, NV>>>(b_dense, Wx, b_lstm);
    prep_M_kernel<<<KROWS / RPB, 512>>>(Wd, Wx);
    ctx_kernel<<<BATCH, 64>>>(last_rule, move_count, node_count, problem_type, out, out_size);

    const int off_lv = BATCH * 35;                 // 4480
    const int off_h  = off_lv + BATCH * UNITS;     // 20864
    lstm_kernel<<<GRID, NT, SMEM_LSTM>>>(bwd, fwd, lbwd, lfwd, Wh,
                                         out + off_h, out + off_lv);
}

// round 8
// speedup vs baseline: 1.8533x; 1.8533x over previous
#include <cuda_runtime.h>
#include <cuda_fp16.h>

#define BATCH 128
#define SEQ   256
#define UNITS 128
#define NV    512          // 4*UNITS gate width
#define DEPTH 655
#define KROWS 2620         // 4*DEPTH
#define NT    256          // threads per lstm block
#define RROWS 96           // Wh rows register-resident per column (fp32)
#define SROWS (UNITS - RROWS)   // 32 rows in smem (fp16)
#define RPAIR (RROWS / 2)       // 48 row-pairs per column in registers
#define RGRP4 (RROWS / 4)       // 24 register groups of 4 rows
#define SGRP8 (SROWS / 8)       // 4 smem groups of 8 rows

// Precomputed M = W_dense @ Wx  [KROWS][NV], plus row KROWS = b_dense@Wx + b_lstm
__device__ float g_M[(KROWS + 1) * NV];

typedef unsigned long long ull;

#define FMA2(acc, a, b) \
    asm("fma.rn.f32x2 %0, %1, %2, %0;" : "+l"(acc) : "l"(a), "l"(b))

__device__ __forceinline__ ull pk(float lo, float hi) {
    return (ull)__float_as_uint(lo) | ((ull)__float_as_uint(hi) << 32);
}
__device__ __forceinline__ float red2(ull a, ull b) {
    ull s;
    asm("add.rn.f32x2 %0, %1, %2;" : "=l"(s) : "l"(a), "l"(b));
    return __uint_as_float((unsigned)s) + __uint_as_float((unsigned)(s >> 32));
}
__device__ __forceinline__ float sigmoid_f(float x) {
    return __fdividef(1.f, 1.f + __expf(-x));
}
__device__ __forceinline__ float tanh_f(float x) {
    return 1.f - __fdividef(2.f, __expf(2.f * x) + 1.f);
}
// fp16 pair (packed in u32) -> packed f32x2 operand
__device__ __forceinline__ ull h2f2(unsigned u) {
    float2 f = __half22float2(*reinterpret_cast<const __half2*>(&u));
    return pk(f.x, f.y);
}
__device__ __forceinline__ unsigned f2h2(float a, float b) {
    __half2 h = __floats2half2_rn(a, b);
    return *reinterpret_cast<unsigned*>(&h);
}

// ---------------------------------------------------------------------------
__global__ void prep_bb_kernel(const float* __restrict__ b_dense,
                               const float* __restrict__ Wx,
                               const float* __restrict__ b_lstm) {
    int t = threadIdx.x;
    float acc = 0.f;
#pragma unroll 8
    for (int u = 0; u < UNITS; ++u)
        acc = fmaf(b_dense[u], Wx[u * NV + t], acc);
    g_M[KROWS * NV + t] = acc + b_lstm[t];
}

// ---------------------------------------------------------------------------
#define RPB 20
__global__ __launch_bounds__(512) void prep_M_kernel(const float* __restrict__ Wd,
                                                     const float* __restrict__ Wx) {
    __shared__ float wd[RPB * UNITS];
    const int t = threadIdx.x;
    const int r0 = blockIdx.x * RPB;
    for (int idx = t; idx < RPB * UNITS; idx += 512)
        wd[idx] = Wd[r0 * UNITS + idx];
    __syncthreads();

    float acc[RPB];
#pragma unroll
    for (int r = 0; r < RPB; ++r) acc[r] = 0.f;

    for (int u = 0; u < UNITS; u += 4) {
        float x0 = Wx[(u + 0) * NV + t];
        float x1 = Wx[(u + 1) * NV + t];
        float x2 = Wx[(u + 2) * NV + t];
        float x3 = Wx[(u + 3) * NV + t];
#pragma unroll
        for (int r = 0; r < RPB; ++r) {
            float4 w = *(const float4*)&wd[r * UNITS + u];
            acc[r] = fmaf(w.x, x0, fmaf(w.y, x1, fmaf(w.z, x2, fmaf(w.w, x3, acc[r]))));
        }
    }
#pragma unroll
    for (int r = 0; r < RPB; ++r)
        g_M[(r0 + r) * NV + t] = acc[r];
}

// ---------------------------------------------------------------------------
__global__ void ctx_kernel(const int* __restrict__ last_rule,
                           const int* __restrict__ move_count,
                           const int* __restrict__ node_count,
                           const int* __restrict__ problem_type,
                           float* __restrict__ out, int out_size) {
    const int b = blockIdx.x, j = threadIdx.x;
    if (j < 35) {
        float v;
        if (j == 0)      v = (float)last_rule[b];
        else if (j == 1) v = (float)move_count[b];
        else if (j == 2) v = (float)node_count[b];
        else             v = (problem_type[b] == (j - 3)) ? 1.f : 0.f;
        out[b * 35 + j] = v;
    }
    const int seq_off = BATCH * 35 + BATCH * UNITS + BATCH * SEQ * UNITS;
    if (b == 0 && j == 63 && out_size > seq_off)
        out[seq_off] = (float)SEQ;
}

// ---------------------------------------------------------------------------
// LSTM: one block per batch row; 256 threads. Warp w covers elements
// [16w,16w+16). Lane l<16 owns element e=16w+l with gate cols (e, e+256)
// = (i, g); lane l+16 owns (e+128, e+384) = (f, o). After activations, two
// shfl.xor(16) bring f,o to the (i,g) lane which computes c,h in registers.
// h published via ping-pong smem buffers -> ONE __syncthreads per step.
// Wh rows [0,RROWS) register-resident fp32 (f32x2 pairs per column); rows
// [RROWS,128) in smem as fp16 (uint4 = 8 rows per column per load).
// ---------------------------------------------------------------------------
#define WH_HALF (SGRP8 * NT * 16)      // 16 KB per column-set (fp16)
#define SMEM_LSTM (2 * WH_HALF + 2 * UNITS * 4 + 4 * SEQ * 4)

__global__ __launch_bounds__(NT, 1) void lstm_kernel(
    const int* __restrict__ bwd, const int* __restrict__ fwd,
    const int* __restrict__ lbwd, const int* __restrict__ lfwd,
    const float* __restrict__ Wh,
    float* __restrict__ out_h,    // [B][S][UNITS]
    float* __restrict__ out_lv) { // [B][UNITS]
    extern __shared__ unsigned char smraw[];
    uint4* whA = (uint4*)smraw;
    uint4* whB = (uint4*)(smraw + WH_HALF);
    float* h0  = (float*)(smraw + 2 * WH_HALF);
    float* h1  = h0 + UNITS;
    int*   idx_s = (int*)(h1 + UNITS);

    const int b = blockIdx.x;
    const int t = threadIdx.x;
    const int l = t & 31;
    const int role = l >> 4;                 // 0: (i,g) owner, 1: (f,o) owner
    const int e  = (t >> 5) * 16 + (l & 15); // element in [0,128)
    const int cA = e + role * 128;           // i (role0) / f (role1)
    const int cB = cA + 256;                 // g (role0) / o (role1)

    // ---- weights: rows [0,RROWS) -> fp32 register pairs per column ----
    ull wA[RPAIR], wB[RPAIR];
#pragma unroll
    for (int p = 0; p < RPAIR; ++p) {
        int i = 2 * p;
        wA[p] = pk(Wh[i * NV + cA], Wh[(i + 1) * NV + cA]);
        wB[p] = pk(Wh[i * NV + cB], Wh[(i + 1) * NV + cB]);
    }
    // rows [RROWS,128) -> smem fp16, 8 rows per uint4 per column
#pragma unroll
    for (int g = 0; g < SGRP8; ++g) {
        int i = RROWS + 8 * g;
        uint4 vA, vB;
        vA.x = f2h2(Wh[(i + 0) * NV + cA], Wh[(i + 1) * NV + cA]);
        vA.y = f2h2(Wh[(i + 2) * NV + cA], Wh[(i + 3) * NV + cA]);
        vA.z = f2h2(Wh[(i + 4) * NV + cA], Wh[(i + 5) * NV + cA]);
        vA.w = f2h2(Wh[(i + 6) * NV + cA], Wh[(i + 7) * NV + cA]);
        vB.x = f2h2(Wh[(i + 0) * NV + cB], Wh[(i + 1) * NV + cB]);
        vB.y = f2h2(Wh[(i + 2) * NV + cB], Wh[(i + 3) * NV + cB]);
        vB.z = f2h2(Wh[(i + 4) * NV + cB], Wh[(i + 5) * NV + cB]);
        vB.w = f2h2(Wh[(i + 6) * NV + cB], Wh[(i + 7) * NV + cB]);
        whA[g * NT + t] = vA;
        whB[g * NT + t] = vB;
    }

    // ---- stage gather indices with offsets pre-added (t covers SEQ=256) ----
    idx_s[t]           = bwd[b * SEQ + t];
    idx_s[SEQ + t]     = DEPTH     + fwd[b * SEQ + t];
    idx_s[2 * SEQ + t] = 2 * DEPTH + lbwd[b * SEQ + t];
    idx_s[3 * SEQ + t] = 3 * DEPTH + lfwd[b * SEQ + t];
    if (t < UNITS) h0[t] = 0.f;
    float c_r = 0.f, h_last = 0.f;
    const float bbA = g_M[KROWS * NV + cA];
    const float bbB = g_M[KROWS * NV + cB];
    __syncthreads();

    // xz for s = 0 (both columns, registers)
    float xzA = g_M[idx_s[0] * NV + cA] + g_M[idx_s[SEQ] * NV + cA] +
                g_M[idx_s[2 * SEQ] * NV + cA] + g_M[idx_s[3 * SEQ] * NV + cA] + bbA;
    float xzB = g_M[idx_s[0] * NV + cB] + g_M[idx_s[SEQ] * NV + cB] +
                g_M[idx_s[2 * SEQ] * NV + cB] + g_M[idx_s[3 * SEQ] * NV + cB] + bbB;

    for (int s = 0; s < SEQ; ++s) {
        // prefetch next step's xz components (L2-resident table)
        const int sn = (s + 1 < SEQ) ? s + 1 : s;
        float mA0 = g_M[idx_s[sn] * NV + cA];
        float mA1 = g_M[idx_s[SEQ + sn] * NV + cA];
        float mA2 = g_M[idx_s[2 * SEQ + sn] * NV + cA];
        float mA3 = g_M[idx_s[3 * SEQ + sn] * NV + cA];
        float mB0 = g_M[idx_s[sn] * NV + cB];
        float mB1 = g_M[idx_s[SEQ + sn] * NV + cB];
        float mB2 = g_M[idx_s[2 * SEQ + sn] * NV + cB];
        float mB3 = g_M[idx_s[3 * SEQ + sn] * NV + cB];

        // z = xz + h . Wh[:,c]  for cA and cB (4 independent f32x2 chains)
        const ulonglong2* hp = (const ulonglong2*)((s & 1) ? h1 : h0);
        ull aA0 = pk(xzA, 0.f), aA1 = 0ull;
        ull aB0 = pk(xzB, 0.f), aB1 = 0ull;
#pragma unroll
        for (int g = 0; g < RGRP4; ++g) {       // 24 groups x 4 rows = 96 rows
            ulonglong2 hv = hp[g];              // broadcast LDS.128
            FMA2(aA0, hv.x, wA[2 * g]);
            FMA2(aA1, hv.y, wA[2 * g + 1]);
            FMA2(aB0, hv.x, wB[2 * g]);
            FMA2(aB1, hv.y, wB[2 * g + 1]);
        }
#pragma unroll
        for (int g = 0; g < SGRP8; ++g) {       // 4 groups x 8 rows = 32 rows
            ulonglong2 hv0 = hp[RGRP4 + 2 * g];     // broadcast LDS.128
            ulonglong2 hv1 = hp[RGRP4 + 2 * g + 1]; // broadcast LDS.128
            uint4 a4 = whA[g * NT + t];             // 8 fp16 weights, col cA
            uint4 b4 = whB[g * NT + t];             // 8 fp16 weights, col cB
            FMA2(aA0, hv0.x, h2f2(a4.x));
            FMA2(aA1, hv0.y, h2f2(a4.y));
            FMA2(aA0, hv1.x, h2f2(a4.z));
            FMA2(aA1, hv1.y, h2f2(a4.w));
            FMA2(aB0, hv0.x, h2f2(b4.x));
            FMA2(aB1, hv0.y, h2f2(b4.y));
            FMA2(aB0, hv1.x, h2f2(b4.z));
            FMA2(aB1, hv1.y, h2f2(b4.w));
        }
        float zA = red2(aA0, aA1);
        float zB = red2(aB0, aB1);

        // activations: cA is i or f -> sigmoid; cB is g (tanh) or o (sigmoid)
        float actA = sigmoid_f(zA);
        float actB = role ? sigmoid_f(zB) : tanh_f(zB);

        // exchange: (i,g) lane receives (f,o) from lane+16
        float xf = __shfl_xor_sync(0xffffffffu, actA, 16);
        float xo = __shfl_xor_sync(0xffffffffu, actB, 16);

        float* hw = (s & 1) ? h0 : h1;
        if (role == 0) {
            float cn = fmaf(xf, c_r, actA * actB);   // f*c + i*g
            c_r = cn;
            float hn = xo * tanh_f(cn);
            hw[e] = hn;
            out_h[(b * SEQ + s) * UNITS + e] = hn;
            h_last = hn;
        }
        xzA = mA0 + mA1 + mA2 + mA3 + bbA;
        xzB = mB0 + mB1 + mB2 + mB3 + bbB;
        __syncthreads();
    }
    if (role == 0) out_lv[b * UNITS + e] = h_last;
}

// ---------------------------------------------------------------------------
extern "C" void kernel_launch(void* const* d_in, const int* in_sizes, int n_in,
                              void* d_out, int out_size) {
    const int*   move_count   = (const int*)d_in[0];
    // d_in[1] = moves_remaining (unused by reference)
    const int*   last_rule    = (const int*)d_in[2];
    const int*   node_count   = (const int*)d_in[3];
    const int*   problem_type = (const int*)d_in[4];
    const int*   bwd          = (const int*)d_in[5];
    const int*   fwd          = (const int*)d_in[6];
    const int*   lbwd         = (const int*)d_in[7];
    const int*   lfwd         = (const int*)d_in[8];
    const float* Wd           = (const float*)d_in[9];
    const float* b_dense      = (const float*)d_in[10];
    const float* Wx           = (const float*)d_in[11];
    const float* Wh           = (const float*)d_in[12];
    const float* b_lstm       = (const float*)d_in[13];
    float* out = (float*)d_out;

    cudaFuncSetAttribute(lstm_kernel, cudaFuncAttributeMaxDynamicSharedMemorySize,
                         SMEM_LSTM);

    prep_bb_kernel<<<1, NV>>>(b_dense, Wx, b_lstm);
    prep_M_kernel<<<KROWS / RPB, 512>>>(Wd, Wx);
    ctx_kernel<<<BATCH, 64>>>(last_rule, move_count, node_count, problem_type, out, out_size);

    const int off_lv = BATCH * 35;                 // 4480
    const int off_h  = off_lv + BATCH * UNITS;     // 20864
    lstm_kernel<<<BATCH, NT, SMEM_LSTM>>>(bwd, fwd, lbwd, lfwd, Wh,
                                          out + off_h, out + off_lv);
}